// round 12
// baseline (speedup 1.0000x reference)
#include <cuda_runtime.h>
#include <math_constants.h>

#define IMG_H 64
#define IMG_W 2048
#define KNN_CUTOFF 1.0f

#define PTS_PER_WARP 6            // 30 active lanes, 2 idle
#define WARPS_PER_BLK 8
#define THREADS_FUSED (WARPS_PER_BLK * 32)          // 256
#define PTS_PER_BLK (WARPS_PER_BLK * PTS_PER_WARP)  // 48

// inv_g[k] = 1 - gauss(k)/sum(gauss), sigma=1, 5x5, row-major (ky,kx)
__device__ __constant__ float INV_G_C[25] = {
    0.99703098f, 0.98669378f, 0.97806177f, 0.98669378f, 0.99703098f,
    0.98669378f, 0.94036569f, 0.90167956f, 0.94036569f, 0.98669378f,
    0.97806177f, 0.90167956f, 0.83789717f, 0.90167956f, 0.97806177f,
    0.98669378f, 0.94036569f, 0.90167956f, 0.94036569f, 0.98669378f,
    0.99703098f, 0.98669378f, 0.97806177f, 0.98669378f, 0.99703098f
};

// ---------------------------------------------------------------------------
// COLD path (~65 of 131072 points): exact top-5 with reference tie-breaking.
// __noinline__ so its registers don't pollute the hot path.
// ---------------------------------------------------------------------------
__device__ __noinline__
unsigned knn_exact_top5(const float* __restrict__ proj_range,
                        int x0, int y0, float ur)
{
    unsigned key[25];
    unsigned ib = 0;
#pragma unroll
    for (int k = 0; k < 25; ++k) {
        const int yy = y0 + (k / 5) - 2;
        const int xx = x0 + (k % 5) - 2;
        const bool valid = ((unsigned)yy < (unsigned)IMG_H) &&
                           ((unsigned)xx < (unsigned)IMG_W);
        const int yyc = valid ? yy : 0;
        const int xxc = valid ? xx : 0;
        float rr = valid ? __ldg(proj_range + yyc * IMG_W + xxc) : 0.0f;
        if (rr < 0.0f) rr = CUDART_INF_F;   // matches reference
        if (k == 12)   rr = ur;             // center: d = 0
        key[k] = __float_as_uint(fabsf(rr - ur) * INV_G_C[k]);
        if (valid) ib |= (1u << k);
    }

    unsigned nm = 0;
#pragma unroll
    for (int sel = 0; sel < 5; ++sel) {
        unsigned long long best = ~0ull;
#pragma unroll
        for (int k = 0; k < 25; ++k) {
            const unsigned long long c =
                ((unsigned long long)key[k] << 32) | (unsigned)k;
            if (c < best) best = c;
        }
        const unsigned bi = (unsigned)(best & 0xFFFFFFFFu);
        nm |= (1u << bi);     // all 5 winners have d <= cutoff (>5 passers exist)
#pragma unroll
        for (int k = 0; k < 25; ++k)
            if ((unsigned)k == bi) key[k] = 0xFFFFFFFFu;
    }

    return nm & ib;           // OOB winners contribute zero probs: drop
}

// ---------------------------------------------------------------------------
// Fused kernel: 5 lanes/point, 6 points/warp (lanes 30,31 idle).
// Phase 1 (role = window row): build cutoff mask; combine via warp shuffles
// (NO smem, NO __syncthreads -> warps fully decoupled).
// Phase 2 (role = channel chunk): gather probs for mask winners, store.
// Rare overflow (>5 cutoff passers, ~5e-4): cold-path exact top-5.
// ---------------------------------------------------------------------------
__global__ __launch_bounds__(THREADS_FUSED, 6)
void knn_fused(const float*  __restrict__ proj_range,
               const float*  __restrict__ unproj,
               const float4* __restrict__ probs4,    // [H*W][5] float4
               const int*    __restrict__ px,
               const int*    __restrict__ py,
               float4*       __restrict__ out4,      // [P][5] float4
               int P)
{
    const int tid   = threadIdx.x;
    const int wrp   = tid >> 5;
    const int lane  = tid & 31;
    const int g     = (lane * 205) >> 10;      // lane / 5 (0..6)
    const int r     = lane - g * 5;            // role: row / channel chunk
    const int p     = blockIdx.x * PTS_PER_BLK + wrp * PTS_PER_WARP + g;
    const bool active = (lane < 30) && (p < P);

    int x0 = 0, y0 = 0;
    float ur = 0.0f;

    // ---------------- phase 1: this lane's window row --------------------
    unsigned partAll = 0, partIB = 0;
    if (active) {
        x0 = px[p];
        y0 = py[p];
        ur = unproj[p];

        const int yy  = y0 + r - 2;
        const bool rv = ((unsigned)yy < (unsigned)IMG_H);
        const int yyc = rv ? yy : 0;

        if (x0 >= 2 && x0 <= IMG_W - 3) {
            const int xb   = x0 - 2;
            const int base = xb & ~3;          // aligned; W%4==0 so in-range
            const bool b1  = (xb & 2) != 0;
            const bool b0  = (xb & 1) != 0;
            const float4* rp = (const float4*)(proj_range + yyc * IMG_W + base);
            const float4 lo = __ldg(rp);
            const float4 hi = __ldg(rp + 1);
            const float h0 = b1 ? lo.z : lo.x;
            const float h1 = b1 ? lo.w : lo.y;
            const float h2 = b1 ? hi.x : lo.z;
            const float h3 = b1 ? hi.y : lo.w;
            const float h4 = b1 ? hi.z : hi.x;
            const float h5 = b1 ? hi.w : hi.y;
            float wv[5];
            wv[0] = b0 ? h1 : h0;
            wv[1] = b0 ? h2 : h1;
            wv[2] = b0 ? h3 : h2;
            wv[3] = b0 ? h4 : h3;
            wv[4] = b0 ? h5 : h4;
#pragma unroll
            for (int i = 0; i < 5; ++i) {
                const int k = r * 5 + i;
                const float rr = rv ? wv[i] : 0.0f;   // OOB row = unfold zero-pad
                const float d  = fabsf(rr - ur) * INV_G_C[k];
                const bool pass = (d <= KNN_CUTOFF) && (rr >= 0.0f);
                if (pass)       partAll |= (1u << k);
                if (pass && rv) partIB  |= (1u << k);
            }
        } else {
            // edge columns (~0.25%): scalar clamped loads for this row
#pragma unroll
            for (int i = 0; i < 5; ++i) {
                const int k  = r * 5 + i;
                const int xx = x0 + i - 2;
                const bool valid = rv && ((unsigned)xx < (unsigned)IMG_W);
                const int xxc = valid ? xx : 0;
                const float rawr = __ldg(proj_range + yyc * IMG_W + xxc);
                const float rr = valid ? rawr : 0.0f;
                const float d  = fabsf(rr - ur) * INV_G_C[k];
                const bool pass = (d <= KNN_CUTOFF) && (rr >= 0.0f);
                if (pass)          partAll |= (1u << k);
                if (pass && valid) partIB  |= (1u << k);
            }
        }
    }

    // ---------------- combine within 5-lane group via shuffles ----------
    // All 32 lanes participate (full mask); idle lanes carry zeros.
    const int gb = lane - r;                   // group base lane
    unsigned maskAll = partAll;
    unsigned maskIB  = partIB;
#pragma unroll
    for (int j = 1; j < 5; ++j) {
        const int src = gb + ((r + j >= 5) ? (r + j - 5) : (r + j));
        maskAll |= __shfl_sync(0xFFFFFFFFu, partAll, src);
        maskIB  |= __shfl_sync(0xFFFFFFFFu, partIB,  src);
    }

    if (!active) return;

    maskAll |= (1u << 12);   // center: d forced 0, always passes, in-bounds
    maskIB  |= (1u << 12);

    // rare overflow: all 5 lanes of this point recompute exactly (cold fn)
    if (__popc(maskAll) > 5) {
        maskIB = knn_exact_top5(proj_range, x0, y0, ur);
    }

    // ---------------- phase 2: gather channel chunk r --------------------
    const int base = y0 * IMG_W + x0;

    int kk[5];
    {
        unsigned mm = maskIB;
#pragma unroll
        for (int i = 0; i < 5; ++i) {
            kk[i] = __ffs(mm) - 1;             // -1 when exhausted
            mm &= mm - 1;
        }
    }

    // accumulate on arrival (no float4 v[5] array -> fewer live registers)
    float4 acc = make_float4(0.f, 0.f, 0.f, 0.f);
#pragma unroll
    for (int i = 0; i < 5; ++i) {
        const int k  = kk[i];
        const int ky = (k * 205) >> 10;        // k/5 for k in [0,24]
        const int idx = base + k + ky * 2043 - 4098;  // = base+(ky-2)*W+(kx-2)
        if (k >= 0) {
            const float4 v = __ldg(probs4 + (size_t)idx * 5 + r);
            acc.x += v.x; acc.y += v.y; acc.z += v.z; acc.w += v.w;
        }
    }

    out4[(size_t)p * 5 + r] = acc;             // coalesced 80B per point
}

extern "C" void kernel_launch(void* const* d_in, const int* in_sizes, int n_in,
                              void* d_out, int out_size)
{
    const float*  proj_range = (const float*)  d_in[0];
    const float*  unproj     = (const float*)  d_in[1];
    const float4* probs4     = (const float4*) d_in[2];
    const int*    px         = (const int*)    d_in[3];
    const int*    py         = (const int*)    d_in[4];
    float4*       out4       = (float4*)       d_out;

    const int P = in_sizes[1];           // unproj_range element count
    const int blocks = (P + PTS_PER_BLK - 1) / PTS_PER_BLK;
    knn_fused<<<blocks, THREADS_FUSED>>>(proj_range, unproj, probs4,
                                         px, py, out4, P);
}